// round 6
// baseline (speedup 1.0000x reference)
#include <cuda_runtime.h>
#include <math.h>

#define NN 128
#define PITCHD 130   // float2 pitch: conflict-free LDS.128 row reads
#define BATCH 512
#define NPAIRS 8128
#define NT 1024
#define NG 8          // j-groups
#define SEGJ 16       // j's per thread
#define TSTEPS 10

struct __align__(16) Smem {
  float2 DW[NN * PITCHD];   // (d,w) pairs, row-major, symmetric
  float4 Xs[NN];            // coordinates, .w = |x|^2
  float4 part[(NG - 1) * NN]; // cross-group partials (x,y,z=sum coef*xj, w=sum coef)
  unsigned bits[NN * 4];    // adjacency bitmask
  float rs[NN];             // row sums of D^2
  float u[NN];              // power-iteration vector
  float scal[8];
  int icnt[4];
};

__device__ __forceinline__ float softplus_f(float x) {
  // softplus = max(x,0) + log(1 + exp(-|x|)); arg of log in (1,2] -> __logf ok
  return fmaxf(x, 0.0f) + __logf(1.0f + __expf(-fabsf(x)));
}

__global__ void __launch_bounds__(NT, 1)
ts_gcn_kernel(const float* __restrict__ edge_pred,
              const int*   __restrict__ adj,
              const float* __restrict__ d_init,
              const float* __restrict__ u_init,
              const float* __restrict__ x_noise,
              float*       __restrict__ out)
{
  extern __shared__ __align__(16) char smem_raw[];
  Smem* sm = reinterpret_cast<Smem*>(smem_raw);
  const int b    = blockIdx.x;
  const int tid  = threadIdx.x;
  const int lane = tid & 31;
  const int wid  = tid >> 5;
  const int i_d  = tid & (NN - 1);
  const int g    = tid >> 7;        // j-group 0..7
  const int j0   = g * SEGJ;
  const float d0 = __ldg(d_init);

  const float2* epb  = reinterpret_cast<const float2*>(edge_pred) + (size_t)b * NN * NN;
  const int*    adjb = adj + (size_t)b * NN * NN;

  if (tid == 0) sm->icnt[0] = 0;

  // ---- A1: stage raw edge_pred (coalesced LDG.64 -> STS) -------------------
  #pragma unroll
  for (int v = 0; v < 16; ++v) {
    int idx = v * NT + tid;
    sm->DW[(idx >> 7) * PITCHD + (idx & (NN - 1))] = epb[idx];
  }
  // ---- A1b: adjacency bits via ballot (no atomics) --------------------------
  #pragma unroll
  for (int v = 0; v < 16; ++v) {
    int word = v * 32 + wid;                 // 512 words total
    int i = word >> 2, q = word & 3;
    int a = adjb[i * NN + q * 32 + lane];    // coalesced 128B per warp
    unsigned m = __ballot_sync(0xffffffffu, a != 0);
    if (lane == 0) sm->bits[word] = m;
  }
  __syncthreads();

  // ---- A2: symmetrize + softplus over upper triangle (closed-form fold) ----
  #pragma unroll
  for (int v = 0; v < 8; ++v) {
    int p = v * NT + tid;                    // p in [0, 8192)
    if (p < NPAIRS) {                        // guard: 8192 > 8128 slots
      int r = p / 127, c = p - r * 127;
      int i, j;
      if (c >= r) { i = r; j = c + 1; }
      else        { i = 127 - r; j = 127 - c; }
      unsigned on = (sm->bits[(i << 2) + (j >> 5)] >> (j & 31)) & 1u;
      float2 e1 = sm->DW[i * PITCHD + j];
      float2 e2 = sm->DW[j * PITCHD + i];
      float2 dw = make_float2(0.0f, 0.0f);
      if (on) {
        dw.x = softplus_f(d0 + e1.x + e2.x);
        dw.y = softplus_f(d0 + e1.y + e2.y);
      }
      sm->DW[i * PITCHD + j] = dw;
      sm->DW[j * PITCHD + i] = dw;
    }
  }
  if (tid < NN) sm->DW[tid * PITCHD + tid] = make_float2(0.0f, 0.0f);
  __syncthreads();

  // ---- B: sum(adj) + row sums of D^2 ---------------------------------------
  if (tid < NN * 4) {
    int cbit = __popc(sm->bits[tid]);
    #pragma unroll
    for (int o = 16; o; o >>= 1) cbit += __shfl_xor_sync(0xffffffffu, cbit, o);
    if (lane == 0) atomicAdd(&sm->icnt[0], cbit);
  }
  {
    float rp = 0.0f;
    const float4* drow = reinterpret_cast<const float4*>(sm->DW + i_d * PITCHD + j0);
    #pragma unroll
    for (int t = 0; t < 8; ++t) {
      float4 q = drow[t];                    // (d,w,d,w)
      rp = fmaf(q.x, q.x, rp);
      rp = fmaf(q.z, q.z, rp);
    }
    if (g) sm->part[(g - 1) * NN + i_d].x = rp;
    __syncthreads();
    if (g == 0) {
      #pragma unroll
      for (int r = 0; r < NG - 1; ++r) rp += sm->part[r * NN + i_d].x;
      sm->rs[i_d] = rp;
    }
  }
  __syncthreads();
  if (tid < 32) {
    float m = sm->rs[tid] + sm->rs[tid + 32] + sm->rs[tid + 64] + sm->rs[tid + 96];
    #pragma unroll
    for (int o = 16; o; o >>= 1) m += __shfl_xor_sync(0xffffffffu, m, o);
    if (tid == 0) {
      float Nmol = 1.0f + (float)(__popc(sm->bits[0]) + __popc(sm->bits[1]) +
                                  __popc(sm->bits[2]) + __popc(sm->bits[3]));
      float invN = 1.0f / Nmol;
      sm->scal[0] = invN;
      sm->scal[1] = m * invN * invN;
      float S = 128.0f + (float)sm->icnt[0];
      sm->scal[2] = 0.4f / S;                // 4*STEP_EPS / sum(mask)
    }
  }
  __syncthreads();

  // ---- B2: Gram matrix directly into REGISTERS -----------------------------
  float bg[SEGJ];
  {
    float invN = sm->scal[0], Moff = sm->scal[1];
    float rsi = sm->rs[i_d];
    unsigned wb = sm->bits[(i_d << 2) + (j0 >> 5)];
    const float4* drow = reinterpret_cast<const float4*>(sm->DW + i_d * PITCHD + j0);
    const float4* rsj  = reinterpret_cast<const float4*>(sm->rs + j0);
    #pragma unroll
    for (int t = 0; t < 4; ++t) {
      float4 rq = rsj[t];
      float4 q0 = drow[2 * t], q1 = drow[2 * t + 1];
      float dv[4] = {q0.x, q0.z, q1.x, q1.z};
      float rv[4] = {rq.x, rq.y, rq.z, rq.w};
      #pragma unroll
      for (int m = 0; m < 4; ++m) {
        int jj = 4 * t + m;
        int j = j0 + jj;
        bool on = (((wb >> (j & 31)) & 1u) != 0u) || (j == i_d);
        float val = -0.5f * (fmaf(dv[m], dv[m], Moff) - (rsi + rv[m]) * invN);
        bg[jj] = on ? val : 0.0f;
      }
    }
  }

  // ---- C: rank-3 power iteration, BG in regs, redundant norms --------------
  for (int k = 0; k < 3; ++k) {
    __syncthreads();
    if (tid < NN) sm->u[tid] = u_init[((size_t)b * NN + tid) * 3 + k];
    __syncthreads();
    for (int it = 0; it < 10; ++it) {
      float4 uv = reinterpret_cast<const float4*>(sm->u)[lane];
      float s = fmaf(uv.x, uv.x, fmaf(uv.y, uv.y, fmaf(uv.z, uv.z, uv.w * uv.w)));
      #pragma unroll
      for (int o = 16; o; o >>= 1) s += __shfl_xor_sync(0xffffffffu, s, o);
      float invn = 1.0f / fmaxf(sqrtf(s), 0.001f);
      float acc = 0.0f;
      const float4* useg = reinterpret_cast<const float4*>(sm->u + j0);
      #pragma unroll
      for (int t = 0; t < 4; ++t) {
        float4 uq = useg[t];
        acc = fmaf(bg[4 * t + 0], uq.x, acc);
        acc = fmaf(bg[4 * t + 1], uq.y, acc);
        acc = fmaf(bg[4 * t + 2], uq.z, acc);
        acc = fmaf(bg[4 * t + 3], uq.w, acc);
      }
      if (g) sm->part[(g - 1) * NN + i_d].x = acc;
      __syncthreads();
      if (g == 0) {
        #pragma unroll
        for (int r = 0; r < NG - 1; ++r) acc += sm->part[r * NN + i_d].x;
        sm->u[i_d] = acc * invn;
      }
      __syncthreads();
    }
    float4 uv = reinterpret_cast<const float4*>(sm->u)[lane];
    float s = fmaf(uv.x, uv.x, fmaf(uv.y, uv.y, fmaf(uv.z, uv.z, uv.w * uv.w)));
    #pragma unroll
    for (int o = 16; o; o >>= 1) s += __shfl_xor_sync(0xffffffffu, s, o);
    float sc4 = rsqrtf(sqrtf(s + 0.01f));    // (eig_sq + 0.01)^-0.25
    __syncthreads();
    if (tid < NN) {
      float uk = sm->u[tid] * sc4;
      sm->u[tid] = uk;
      reinterpret_cast<float*>(&sm->Xs[tid])[k] =
          uk + x_noise[((size_t)b * NN + tid) * 3 + k];
    }
    __syncthreads();
    if (k < 2) {
      float ui = sm->u[i_d];
      const float4* useg = reinterpret_cast<const float4*>(sm->u + j0);
      #pragma unroll
      for (int t = 0; t < 4; ++t) {
        float4 uq = useg[t];
        bg[4 * t + 0] = fmaf(-ui, uq.x, bg[4 * t + 0]);
        bg[4 * t + 1] = fmaf(-ui, uq.y, bg[4 * t + 1]);
        bg[4 * t + 2] = fmaf(-ui, uq.z, bg[4 * t + 2]);
        bg[4 * t + 3] = fmaf(-ui, uq.w, bg[4 * t + 3]);
      }
    }
  }
  // finalize Xs.w = |x|^2
  if (tid < NN) {
    float4 x = sm->Xs[tid];
    x.w = fmaf(x.x, x.x, fmaf(x.y, x.y, x.z * x.z));
    sm->Xs[tid] = x;
  }

  // ---- preload (w*d, w) into registers for all 10 steps ---------------------
  float2 dwr[SEGJ];
  {
    const float4* drow = reinterpret_cast<const float4*>(sm->DW + i_d * PITCHD + j0);
    #pragma unroll
    for (int t = 0; t < 8; ++t) {
      float4 q = drow[t];
      dwr[2 * t]     = make_float2(q.x * q.y, q.y);
      dwr[2 * t + 1] = make_float2(q.z * q.w, q.w);
    }
  }
  const float cc = sm->scal[2];
  __syncthreads();

  // ---- D: 10 gradient-descent steps (dot-product form) ----------------------
  for (int ts = 0; ts < TSTEPS; ++ts) {
    float alpha = 0.1f + 4.9f * ((float)(TSTEPS - ts) * 0.1f);
    float4 xi = sm->Xs[i_d];
    float m2x = -2.0f * xi.x, m2y = -2.0f * xi.y, m2z = -2.0f * xi.z;
    float cbase = xi.w + 0.01f;              // |xi|^2 + 0.01
    float cs = 0.0f, ax = 0.0f, ay = 0.0f, az = 0.0f;
    const float4* xrow = sm->Xs + j0;
    #pragma unroll
    for (int jj = 0; jj < SEGJ; ++jj) {
      float4 xj = xrow[jj];                  // broadcast LDS.128
      float t = fmaf(xj.x, m2x, xj.w);       // |xj|^2 - 2 xi.xj (partial)
      t = fmaf(xj.y, m2y, t);
      t = fmaf(xj.z, m2z, t);
      float s = t + cbase;                   // |xi-xj|^2 + 0.01
      float rinv = rsqrtf(s);
      float coef = fmaf(dwr[jj].x, rinv, -dwr[jj].y);  // w*(d/Dx - 1)
      cs += coef;
      ax = fmaf(coef, xj.x, ax);
      ay = fmaf(coef, xj.y, ay);
      az = fmaf(coef, xj.z, az);
    }
    if (g) sm->part[(g - 1) * NN + i_d] = make_float4(ax, ay, az, cs);
    __syncthreads();
    if (g == 0) {
      #pragma unroll
      for (int r = 0; r < NG - 1; ++r) {
        float4 p = sm->part[r * NN + i_d];
        ax += p.x; ay += p.y; az += p.z; cs += p.w;
      }
      float gx = fmaf(cs, xi.x, -ax) * cc;   // (sum coef*(xi-xj)) * cc
      float gy = fmaf(cs, xi.y, -ay) * cc;
      float gz = fmaf(cs, xi.z, -az) * cc;
      float s2 = fmaf(gx, gx, fmaf(gy, gy, fmaf(gz, gz, 0.001f)));
      float inv_sp = rsqrtf(s2);
      float sp = s2 * inv_sp;
      float e = __expf(2.0f * (sp / alpha));
      float th = 1.0f - __fdividef(2.0f, e + 1.0f);   // tanh(sp/alpha)
      float sc = alpha * th * inv_sp;
      xi.x = fmaf(gx, sc, xi.x);
      xi.y = fmaf(gy, sc, xi.y);
      xi.z = fmaf(gz, sc, xi.z);
      xi.w = fmaf(xi.x, xi.x, fmaf(xi.y, xi.y, xi.z * xi.z));
      sm->Xs[i_d] = xi;
    }
    __syncthreads();
  }

  // ---- E: output = adj * distances(X) (exact differences) -------------------
  float* outb = out + (size_t)b * NN * NN;
  #pragma unroll
  for (int v = 0; v < 4; ++v) {
    int f = v * NT + tid;                    // float4 index
    int i = f >> 5;
    int jb = (f & 31) * 4;
    float4 xi = sm->Xs[i];
    unsigned wb = sm->bits[(i << 2) + (jb >> 5)];
    float4 r;
    #pragma unroll
    for (int m = 0; m < 4; ++m) {
      int j = jb + m;
      float4 xj = sm->Xs[j];
      float dx = xi.x - xj.x, dy = xi.y - xj.y, dz = xi.z - xj.z;
      float s = fmaf(dx, dx, fmaf(dy, dy, fmaf(dz, dz, 0.01f)));
      float val = ((wb >> (j & 31)) & 1u) ? sqrtf(s) : 0.0f;
      reinterpret_cast<float*>(&r)[m] = val;
    }
    reinterpret_cast<float4*>(outb)[f] = r;
  }
}

extern "C" void kernel_launch(void* const* d_in, const int* in_sizes, int n_in,
                              void* d_out, int out_size) {
  const float* edge_pred = (const float*)d_in[0];
  const int*   adj       = (const int*)  d_in[1];
  const float* d_init    = (const float*)d_in[2];
  const float* u_init    = (const float*)d_in[3];
  const float* x_noise   = (const float*)d_in[4];
  float* out = (float*)d_out;

  size_t smem = sizeof(Smem);
  cudaFuncSetAttribute(ts_gcn_kernel,
                       cudaFuncAttributeMaxDynamicSharedMemorySize, (int)smem);
  ts_gcn_kernel<<<BATCH, NT, smem>>>(edge_pred, adj, d_init, u_init,
                                     x_noise, out);
}

// round 7
// speedup vs baseline: 1.0950x; 1.0950x over previous
#include <cuda_runtime.h>
#include <math.h>

#define NN 128
#define PITCHD 130   // float2 pitch: conflict-free LDS.128 row reads
#define BATCH 512
#define NPAIRS 8128
#define NT 512
#define SEGJ 32
#define TSTEPS 10

typedef unsigned long long ull;

struct __align__(16) Smem {
  float2 DW[NN * PITCHD];   // (d,w) pairs, row-major, symmetric
  float4 Xs[NN];            // coordinates, .w = |x|^2
  float4 part[3 * NN];      // cross-group partials
  float  xsX[NN];           // SoA copies of X for packed loads
  float  xsY[NN];
  float  xsZ[NN];
  float  xsW[NN];
  unsigned bits[NN * 4];    // adjacency bitmask
  float rs[NN];             // row sums of D^2
  float u[NN];              // power-iteration vector
  float scal[8];
  int icnt[4];
};

__device__ __forceinline__ float softplus_f(float x) {
  return fmaxf(x, 0.0f) + __logf(1.0f + __expf(-fabsf(x)));
}

__device__ __forceinline__ ull pk2(float lo, float hi) {
  ull r; asm("mov.b64 %0, {%1, %2};" : "=l"(r) : "f"(lo), "f"(hi)); return r;
}
__device__ __forceinline__ void upk2(ull v, float& lo, float& hi) {
  asm("mov.b64 {%0, %1}, %2;" : "=f"(lo), "=f"(hi) : "l"(v));
}
__device__ __forceinline__ ull fma2(ull a, ull b, ull c) {
  ull d; asm("fma.rn.f32x2 %0, %1, %2, %3;" : "=l"(d) : "l"(a), "l"(b), "l"(c));
  return d;
}
__device__ __forceinline__ ull add2(ull a, ull b) {
  ull d; asm("add.rn.f32x2 %0, %1, %2;" : "=l"(d) : "l"(a), "l"(b));
  return d;
}

__global__ void __launch_bounds__(NT, 1)
ts_gcn_kernel(const float* __restrict__ edge_pred,
              const int*   __restrict__ adj,
              const float* __restrict__ d_init,
              const float* __restrict__ u_init,
              const float* __restrict__ x_noise,
              float*       __restrict__ out)
{
  extern __shared__ __align__(16) char smem_raw[];
  Smem* sm = reinterpret_cast<Smem*>(smem_raw);
  const int b    = blockIdx.x;
  const int tid  = threadIdx.x;
  const int lane = tid & 31;
  const int wid  = tid >> 5;
  const int i_d  = tid & (NN - 1);
  const int g    = tid >> 7;        // j-group 0..3
  const int j0   = g * SEGJ;
  const float d0 = __ldg(d_init);

  const float2* epb  = reinterpret_cast<const float2*>(edge_pred) + (size_t)b * NN * NN;
  const int*    adjb = adj + (size_t)b * NN * NN;

  if (tid == 0) sm->icnt[0] = 0;

  // ---- A1: stage raw edge_pred (coalesced) ----------------------------------
  #pragma unroll
  for (int v = 0; v < 32; ++v) {
    int idx = v * NT + tid;
    sm->DW[(idx >> 7) * PITCHD + (idx & (NN - 1))] = epb[idx];
  }
  // ---- A1b: adjacency bits via ballot ----------------------------------------
  #pragma unroll
  for (int v = 0; v < 32; ++v) {
    int word = v * 16 + wid;
    int i = word >> 2, q = word & 3;
    int a = adjb[i * NN + q * 32 + lane];
    unsigned m = __ballot_sync(0xffffffffu, a != 0);
    if (lane == 0) sm->bits[word] = m;
  }
  __syncthreads();

  // ---- A2: symmetrize + softplus over upper triangle -------------------------
  #pragma unroll
  for (int v = 0; v < 16; ++v) {
    int p = v * NT + tid;
    if (p < NPAIRS) {
      int r = p / 127, c = p - r * 127;
      int i, j;
      if (c >= r) { i = r; j = c + 1; }
      else        { i = 127 - r; j = 127 - c; }
      unsigned on = (sm->bits[(i << 2) + (j >> 5)] >> (j & 31)) & 1u;
      float2 e1 = sm->DW[i * PITCHD + j];
      float2 e2 = sm->DW[j * PITCHD + i];
      float2 dw = make_float2(0.0f, 0.0f);
      if (on) {
        dw.x = softplus_f(d0 + e1.x + e2.x);
        dw.y = softplus_f(d0 + e1.y + e2.y);
      }
      sm->DW[i * PITCHD + j] = dw;
      sm->DW[j * PITCHD + i] = dw;
    }
  }
  if (tid < NN) sm->DW[tid * PITCHD + tid] = make_float2(0.0f, 0.0f);
  __syncthreads();

  // ---- B: sum(adj) + row sums of D^2 -----------------------------------------
  {
    int cbit = __popc(sm->bits[tid]);
    #pragma unroll
    for (int o = 16; o; o >>= 1) cbit += __shfl_xor_sync(0xffffffffu, cbit, o);
    if (lane == 0) atomicAdd(&sm->icnt[0], cbit);
  }
  {
    float rp = 0.0f;
    const float4* drow = reinterpret_cast<const float4*>(sm->DW + i_d * PITCHD + j0);
    #pragma unroll
    for (int t = 0; t < 16; ++t) {
      float4 q = drow[t];
      rp = fmaf(q.x, q.x, rp);
      rp = fmaf(q.z, q.z, rp);
    }
    if (g) sm->part[(g - 1) * NN + i_d].x = rp;
    __syncthreads();
    if (g == 0) {
      rp += sm->part[i_d].x + sm->part[NN + i_d].x + sm->part[2 * NN + i_d].x;
      sm->rs[i_d] = rp;
    }
  }
  __syncthreads();
  if (tid < 32) {
    float m = sm->rs[tid] + sm->rs[tid + 32] + sm->rs[tid + 64] + sm->rs[tid + 96];
    #pragma unroll
    for (int o = 16; o; o >>= 1) m += __shfl_xor_sync(0xffffffffu, m, o);
    if (tid == 0) {
      float Nmol = 1.0f + (float)(__popc(sm->bits[0]) + __popc(sm->bits[1]) +
                                  __popc(sm->bits[2]) + __popc(sm->bits[3]));
      float invN = 1.0f / Nmol;
      sm->scal[0] = invN;
      sm->scal[1] = m * invN * invN;
      float S = 128.0f + (float)sm->icnt[0];
      sm->scal[2] = 0.4f / S;
    }
  }
  __syncthreads();

  // ---- B2: Gram matrix into registers ----------------------------------------
  float bg[SEGJ];
  {
    float invN = sm->scal[0], Moff = sm->scal[1];
    float rsi = sm->rs[i_d];
    unsigned wb = sm->bits[(i_d << 2) + (j0 >> 5)];
    const float4* drow = reinterpret_cast<const float4*>(sm->DW + i_d * PITCHD + j0);
    const float4* rsj  = reinterpret_cast<const float4*>(sm->rs + j0);
    #pragma unroll
    for (int t = 0; t < 8; ++t) {
      float4 rq = rsj[t];
      float4 q0 = drow[2 * t], q1 = drow[2 * t + 1];
      float dv[4] = {q0.x, q0.z, q1.x, q1.z};
      float rv[4] = {rq.x, rq.y, rq.z, rq.w};
      #pragma unroll
      for (int m = 0; m < 4; ++m) {
        int jj = 4 * t + m;
        int j = j0 + jj;
        bool on = (((wb >> jj) & 1u) != 0u) || (j == i_d);
        float val = -0.5f * (fmaf(dv[m], dv[m], Moff) - (rsi + rv[m]) * invN);
        bg[jj] = on ? val : 0.0f;
      }
    }
  }

  // ---- C: rank-3 power iteration ---------------------------------------------
  for (int k = 0; k < 3; ++k) {
    __syncthreads();
    if (tid < NN) sm->u[tid] = u_init[((size_t)b * NN + tid) * 3 + k];
    __syncthreads();
    for (int it = 0; it < 10; ++it) {
      float4 uv = reinterpret_cast<const float4*>(sm->u)[lane];
      float s = fmaf(uv.x, uv.x, fmaf(uv.y, uv.y, fmaf(uv.z, uv.z, uv.w * uv.w)));
      #pragma unroll
      for (int o = 16; o; o >>= 1) s += __shfl_xor_sync(0xffffffffu, s, o);
      float invn = 1.0f / fmaxf(sqrtf(s), 0.001f);
      float acc = 0.0f;
      const float4* useg = reinterpret_cast<const float4*>(sm->u + j0);
      #pragma unroll
      for (int t = 0; t < 8; ++t) {
        float4 uq = useg[t];
        acc = fmaf(bg[4 * t + 0], uq.x, acc);
        acc = fmaf(bg[4 * t + 1], uq.y, acc);
        acc = fmaf(bg[4 * t + 2], uq.z, acc);
        acc = fmaf(bg[4 * t + 3], uq.w, acc);
      }
      if (g) sm->part[(g - 1) * NN + i_d].x = acc;
      __syncthreads();
      if (g == 0) {
        acc += sm->part[i_d].x + sm->part[NN + i_d].x + sm->part[2 * NN + i_d].x;
        sm->u[i_d] = acc * invn;
      }
      __syncthreads();
    }
    float4 uv = reinterpret_cast<const float4*>(sm->u)[lane];
    float s = fmaf(uv.x, uv.x, fmaf(uv.y, uv.y, fmaf(uv.z, uv.z, uv.w * uv.w)));
    #pragma unroll
    for (int o = 16; o; o >>= 1) s += __shfl_xor_sync(0xffffffffu, s, o);
    float sc4 = rsqrtf(sqrtf(s + 0.01f));
    __syncthreads();
    if (tid < NN) {
      float uk = sm->u[tid] * sc4;
      sm->u[tid] = uk;
      reinterpret_cast<float*>(&sm->Xs[tid])[k] =
          uk + x_noise[((size_t)b * NN + tid) * 3 + k];
    }
    __syncthreads();
    if (k < 2) {
      float ui = sm->u[i_d];
      const float4* useg = reinterpret_cast<const float4*>(sm->u + j0);
      #pragma unroll
      for (int t = 0; t < 8; ++t) {
        float4 uq = useg[t];
        bg[4 * t + 0] = fmaf(-ui, uq.x, bg[4 * t + 0]);
        bg[4 * t + 1] = fmaf(-ui, uq.y, bg[4 * t + 1]);
        bg[4 * t + 2] = fmaf(-ui, uq.z, bg[4 * t + 2]);
        bg[4 * t + 3] = fmaf(-ui, uq.w, bg[4 * t + 3]);
      }
    }
  }
  // finalize Xs.w = |x|^2 and SoA copies
  if (tid < NN) {
    float4 x = sm->Xs[tid];
    x.w = fmaf(x.x, x.x, fmaf(x.y, x.y, x.z * x.z));
    sm->Xs[tid] = x;
    sm->xsX[tid] = x.x; sm->xsY[tid] = x.y;
    sm->xsZ[tid] = x.z; sm->xsW[tid] = x.w;
  }

  // ---- preload packed (w*d) and (-w) for all 10 steps ------------------------
  ull wd2[SEGJ / 2], wn2[SEGJ / 2];
  {
    const float4* drow = reinterpret_cast<const float4*>(sm->DW + i_d * PITCHD + j0);
    #pragma unroll
    for (int t = 0; t < 16; ++t) {
      float4 q = drow[t];                    // (d0,w0,d1,w1)
      wd2[t] = pk2(q.x * q.y, q.z * q.w);
      wn2[t] = pk2(-q.y, -q.w);
    }
  }
  const float cc = sm->scal[2];
  __syncthreads();

  // ---- D: 10 gradient-descent steps, packed f32x2 ----------------------------
  for (int ts = 0; ts < TSTEPS; ++ts) {
    float alpha = 0.1f + 4.9f * ((float)(TSTEPS - ts) * 0.1f);
    float4 xi = sm->Xs[i_d];
    ull m2x2 = pk2(-2.0f * xi.x, -2.0f * xi.x);
    ull m2y2 = pk2(-2.0f * xi.y, -2.0f * xi.y);
    ull m2z2 = pk2(-2.0f * xi.z, -2.0f * xi.z);
    float cbase = xi.w + 0.01f;
    ull cbase2 = pk2(cbase, cbase);
    ull cs2 = 0ull, ax2 = 0ull, ay2 = 0ull, az2 = 0ull;
    const ull* pX = reinterpret_cast<const ull*>(sm->xsX + j0);
    const ull* pY = reinterpret_cast<const ull*>(sm->xsY + j0);
    const ull* pZ = reinterpret_cast<const ull*>(sm->xsZ + j0);
    const ull* pW = reinterpret_cast<const ull*>(sm->xsW + j0);
    #pragma unroll
    for (int t = 0; t < SEGJ / 2; ++t) {
      ull xjx = pX[t], xjy = pY[t], xjz = pZ[t], xjw = pW[t];  // LDS.64 bcast
      ull s2p = fma2(xjx, m2x2, xjw);
      s2p = fma2(xjy, m2y2, s2p);
      s2p = fma2(xjz, m2z2, s2p);
      s2p = add2(s2p, cbase2);               // |xi-xj|^2 + 0.01 (two j's)
      float s0, s1;
      upk2(s2p, s0, s1);
      ull r2 = pk2(rsqrtf(s0), rsqrtf(s1));
      ull coef2 = fma2(wd2[t], r2, wn2[t]);  // w*(d/Dx - 1), packed
      cs2 = add2(cs2, coef2);
      ax2 = fma2(coef2, xjx, ax2);
      ay2 = fma2(coef2, xjy, ay2);
      az2 = fma2(coef2, xjz, az2);
    }
    float csl, csh, axl, axh, ayl, ayh, azl, azh;
    upk2(cs2, csl, csh); upk2(ax2, axl, axh);
    upk2(ay2, ayl, ayh); upk2(az2, azl, azh);
    float cs = csl + csh, ax = axl + axh, ay = ayl + ayh, az = azl + azh;
    if (g) sm->part[(g - 1) * NN + i_d] = make_float4(ax, ay, az, cs);
    __syncthreads();
    if (g == 0) {
      float4 p1 = sm->part[i_d], p2 = sm->part[NN + i_d], p3 = sm->part[2 * NN + i_d];
      float AX = ax + p1.x + p2.x + p3.x;
      float AY = ay + p1.y + p2.y + p3.y;
      float AZ = az + p1.z + p2.z + p3.z;
      float CS = cs + p1.w + p2.w + p3.w;
      float gx = fmaf(CS, xi.x, -AX) * cc;
      float gy = fmaf(CS, xi.y, -AY) * cc;
      float gz = fmaf(CS, xi.z, -AZ) * cc;
      float s2 = fmaf(gx, gx, fmaf(gy, gy, fmaf(gz, gz, 0.001f)));
      float inv_sp = rsqrtf(s2);
      float sp = s2 * inv_sp;
      float e = __expf(2.0f * (sp / alpha));
      float th = 1.0f - __fdividef(2.0f, e + 1.0f);
      float sc = alpha * th * inv_sp;
      xi.x = fmaf(gx, sc, xi.x);
      xi.y = fmaf(gy, sc, xi.y);
      xi.z = fmaf(gz, sc, xi.z);
      xi.w = fmaf(xi.x, xi.x, fmaf(xi.y, xi.y, xi.z * xi.z));
      sm->Xs[i_d] = xi;
      sm->xsX[i_d] = xi.x; sm->xsY[i_d] = xi.y;
      sm->xsZ[i_d] = xi.z; sm->xsW[i_d] = xi.w;
    }
    __syncthreads();
  }

  // ---- E: output = adj * distances(X) (exact differences) --------------------
  float* outb = out + (size_t)b * NN * NN;
  #pragma unroll
  for (int v = 0; v < 8; ++v) {
    int f = v * NT + tid;
    int i = f >> 5;
    int jb = (f & 31) * 4;
    float4 xi = sm->Xs[i];
    unsigned wb = sm->bits[(i << 2) + (jb >> 5)];
    float4 r;
    #pragma unroll
    for (int m = 0; m < 4; ++m) {
      int j = jb + m;
      float4 xj = sm->Xs[j];
      float dx = xi.x - xj.x, dy = xi.y - xj.y, dz = xi.z - xj.z;
      float s = fmaf(dx, dx, fmaf(dy, dy, fmaf(dz, dz, 0.01f)));
      float val = ((wb >> (j & 31)) & 1u) ? sqrtf(s) : 0.0f;
      reinterpret_cast<float*>(&r)[m] = val;
    }
    reinterpret_cast<float4*>(outb)[f] = r;
  }
}

extern "C" void kernel_launch(void* const* d_in, const int* in_sizes, int n_in,
                              void* d_out, int out_size) {
  const float* edge_pred = (const float*)d_in[0];
  const int*   adj       = (const int*)  d_in[1];
  const float* d_init    = (const float*)d_in[2];
  const float* u_init    = (const float*)d_in[3];
  const float* x_noise   = (const float*)d_in[4];
  float* out = (float*)d_out;

  size_t smem = sizeof(Smem);
  cudaFuncSetAttribute(ts_gcn_kernel,
                       cudaFuncAttributeMaxDynamicSharedMemorySize, (int)smem);
  ts_gcn_kernel<<<BATCH, NT, smem>>>(edge_pred, adj, d_init, u_init,
                                     x_noise, out);
}